// round 1
// baseline (speedup 1.0000x reference)
#include <cuda_runtime.h>

// Problem dims (fixed by setup_inputs)
#define B_SZ   2
#define S_LEN  2048
#define DMODEL 2048
#define NHEAD  16
#define M_TOK  (B_SZ * S_LEN)     // 4096
#define N_QKV  (3 * DMODEL)       // 6144

// Scratch (static device globals: allocation-free)
__device__ float g_qkv[(size_t)M_TOK * N_QKV];     // 100 MB
__device__ float g_attn[(size_t)M_TOK * DMODEL];   // 33.5 MB

// ---------------------------------------------------------------------------
// SGEMM: C[M,N] = A[M,K] @ B[K,N] + bias[N]   (all row-major fp32)
// 128x128 block, BK=16, 8x8 microtile, 256 threads, double-buffered smem.
// M % 128 == 0, N % 128 == 0, K % 16 == 0 (always true here).
// ---------------------------------------------------------------------------
__global__ __launch_bounds__(256, 2)
void sgemm_bias_kernel(const float* __restrict__ A, const float* __restrict__ B,
                       const float* __restrict__ bias, float* __restrict__ C,
                       int M, int N, int K)
{
    constexpr int BK = 16;
    __shared__ __align__(16) float As[2][BK][132];  // transposed, padded
    __shared__ __align__(16) float Bs[2][BK][128];

    const int tid = threadIdx.x;
    const int tx = tid & 15, ty = tid >> 4;
    const int row0 = blockIdx.y * 128, col0 = blockIdx.x * 128;

    // Global-load mapping (two reps of 256 threads each)
    const int ar0 = tid >> 2;            // 0..63   (+64 for rep 1)
    const int ac0 = (tid & 3) * 4;       // 0,4,8,12
    const int br0 = tid >> 5;            // 0..7    (+8 for rep 1)
    const int bc0 = (tid & 31) * 4;      // 0..124

    const float* Aptr = A + (size_t)row0 * K;
    const float* Bptr = B + col0;

    float acc[8][8];
#pragma unroll
    for (int i = 0; i < 8; i++)
#pragma unroll
        for (int j = 0; j < 8; j++) acc[i][j] = 0.f;

    // Preload tile 0
#pragma unroll
    for (int r = 0; r < 2; r++) {
        float4 va = *(const float4*)(Aptr + (size_t)(ar0 + 64 * r) * K + ac0);
        As[0][ac0 + 0][ar0 + 64 * r] = va.x;
        As[0][ac0 + 1][ar0 + 64 * r] = va.y;
        As[0][ac0 + 2][ar0 + 64 * r] = va.z;
        As[0][ac0 + 3][ar0 + 64 * r] = va.w;
        float4 vb = *(const float4*)(Bptr + (size_t)(br0 + 8 * r) * N + bc0);
        *(float4*)&Bs[0][br0 + 8 * r][bc0] = vb;
    }
    __syncthreads();

    int buf = 0;
    const int T = K / BK;
    for (int t = 0; t < T; ++t) {
        float4 pa[2], pb[2];
        if (t + 1 < T) {
            const int k0 = (t + 1) * BK;
#pragma unroll
            for (int r = 0; r < 2; r++) {
                pa[r] = *(const float4*)(Aptr + (size_t)(ar0 + 64 * r) * K + k0 + ac0);
                pb[r] = *(const float4*)(Bptr + (size_t)(k0 + br0 + 8 * r) * N + bc0);
            }
        }
#pragma unroll
        for (int kk = 0; kk < BK; ++kk) {
            float a[8], b[8];
            *(float4*)&a[0] = *(float4*)&As[buf][kk][ty * 8];
            *(float4*)&a[4] = *(float4*)&As[buf][kk][ty * 8 + 4];
            *(float4*)&b[0] = *(float4*)&Bs[buf][kk][tx * 8];
            *(float4*)&b[4] = *(float4*)&Bs[buf][kk][tx * 8 + 4];
#pragma unroll
            for (int i = 0; i < 8; i++)
#pragma unroll
                for (int j = 0; j < 8; j++)
                    acc[i][j] += a[i] * b[j];
        }
        if (t + 1 < T) {
#pragma unroll
            for (int r = 0; r < 2; r++) {
                As[buf ^ 1][ac0 + 0][ar0 + 64 * r] = pa[r].x;
                As[buf ^ 1][ac0 + 1][ar0 + 64 * r] = pa[r].y;
                As[buf ^ 1][ac0 + 2][ar0 + 64 * r] = pa[r].z;
                As[buf ^ 1][ac0 + 3][ar0 + 64 * r] = pa[r].w;
                *(float4*)&Bs[buf ^ 1][br0 + 8 * r][bc0] = pb[r];
            }
            __syncthreads();
            buf ^= 1;
        }
    }

    // Epilogue: += bias, vectorized stores
#pragma unroll
    for (int i = 0; i < 8; i++) {
        const size_t row = (size_t)(row0 + ty * 8 + i);
#pragma unroll
        for (int j4 = 0; j4 < 2; j4++) {
            const int col = col0 + tx * 8 + j4 * 4;
            float4 bb = *(const float4*)(bias + col);
            float4 o;
            o.x = acc[i][j4 * 4 + 0] + bb.x;
            o.y = acc[i][j4 * 4 + 1] + bb.y;
            o.z = acc[i][j4 * 4 + 2] + bb.z;
            o.w = acc[i][j4 * 4 + 3] + bb.w;
            *(float4*)(C + row * N + col) = o;
        }
    }
}

// ---------------------------------------------------------------------------
// Flash differential attention.
// Grid: (S/64 query blocks, B*H). 256 threads = 16x16 (ty=row group, tx=col group).
// Per thread: 4 query rows (4*ty+i), 4 key cols (4*tx+j) for scores,
//             8 v dims (8*tx+j) for PV. Dual online softmax streams.
// qkv layout: [token][6144] with q1|q2|k1|k2|v packed per reference split.
// ---------------------------------------------------------------------------
#define ATT_SMEM_FLOATS (6 * 64 * 68 + 64 * 128 + 64)
#define ATT_SMEM_BYTES  (ATT_SMEM_FLOATS * 4)

__global__ __launch_bounds__(256, 1)
void diff_attn_kernel(const float* __restrict__ qkv, const float* __restrict__ amask,
                      const float* __restrict__ lambda_p, float* __restrict__ out)
{
    extern __shared__ __align__(16) float sm[];
    float* q1s  = sm;                 // [64][68]
    float* q2s  = q1s + 64 * 68;
    float* k1s  = q2s + 64 * 68;
    float* k2s  = k1s + 64 * 68;
    float* vs   = k2s + 64 * 68;      // [64][128]
    float* p1s  = vs + 64 * 128;      // [64][68]
    float* p2s  = p1s + 64 * 68;
    float* madd = p2s + 64 * 68;      // [64]

    const int tid = threadIdx.x;
    const int tx = tid & 15, ty = tid >> 4;
    const int q0 = blockIdx.x * 64;
    const int bh = blockIdx.y;
    const int b = bh >> 4, h = bh & 15;
    const float scale = 0.0883883476483184f;   // 128^-0.5
    const float lam = *lambda_p;

    const float* base = qkv + (size_t)b * S_LEN * N_QKV;
    const float* q1g = base + h * 64;
    const float* q2g = base + 1024 + h * 64;
    const float* k1g = base + 2048 + h * 64;
    const float* k2g = base + 3072 + h * 64;
    const float* vg  = base + 4096 + h * 128;

    // Load q tiles (pre-scaled)
#pragma unroll
    for (int r = 0; r < 4; r++) {
        int id = tid + r * 256;
        int qi = id >> 4, c4 = (id & 15) * 4;
        float4 v1 = *(const float4*)(q1g + (size_t)(q0 + qi) * N_QKV + c4);
        float4 v2 = *(const float4*)(q2g + (size_t)(q0 + qi) * N_QKV + c4);
        v1.x *= scale; v1.y *= scale; v1.z *= scale; v1.w *= scale;
        v2.x *= scale; v2.y *= scale; v2.z *= scale; v2.w *= scale;
        *(float4*)&q1s[qi * 68 + c4] = v1;
        *(float4*)&q2s[qi * 68 + c4] = v2;
    }

    float o1[4][8], o2[4][8];
    float m1[4], l1[4], m2[4], l2[4];
#pragma unroll
    for (int i = 0; i < 4; i++) {
        m1[i] = -1e30f; l1[i] = 0.f; m2[i] = -1e30f; l2[i] = 0.f;
#pragma unroll
        for (int j = 0; j < 8; j++) { o1[i][j] = 0.f; o2[i][j] = 0.f; }
    }

    for (int kb = 0; kb < S_LEN / 64; ++kb) {
        __syncthreads();   // previous PV done before overwriting k/v/p tiles
        const int k0 = kb * 64;
#pragma unroll
        for (int r = 0; r < 4; r++) {
            int id = tid + r * 256;
            int ki = id >> 4, c4 = (id & 15) * 4;
            *(float4*)&k1s[ki * 68 + c4] = *(const float4*)(k1g + (size_t)(k0 + ki) * N_QKV + c4);
            *(float4*)&k2s[ki * 68 + c4] = *(const float4*)(k2g + (size_t)(k0 + ki) * N_QKV + c4);
        }
#pragma unroll
        for (int r = 0; r < 8; r++) {
            int id = tid + r * 256;
            int ki = id >> 5, c4 = (id & 31) * 4;
            *(float4*)&vs[ki * 128 + c4] = *(const float4*)(vg + (size_t)(k0 + ki) * N_QKV + c4);
        }
        if (tid < 64)
            madd[tid] = (1.0f - amask[(size_t)b * S_LEN + k0 + tid]) * -10000.0f;
        __syncthreads();

        // ---- Scores (register-tiled GEMM, both streams) ----
        float s1[4][4], s2[4][4];
#pragma unroll
        for (int i = 0; i < 4; i++)
#pragma unroll
            for (int j = 0; j < 4; j++) { s1[i][j] = 0.f; s2[i][j] = 0.f; }

#pragma unroll 4
        for (int d4 = 0; d4 < 16; ++d4) {
            float4 qa[4], kv[4];
#pragma unroll
            for (int i = 0; i < 4; i++) qa[i] = *(float4*)&q1s[(4 * ty + i) * 68 + 4 * d4];
#pragma unroll
            for (int j = 0; j < 4; j++) kv[j] = *(float4*)&k1s[(4 * tx + j) * 68 + 4 * d4];
#pragma unroll
            for (int i = 0; i < 4; i++)
#pragma unroll
                for (int j = 0; j < 4; j++)
                    s1[i][j] += qa[i].x * kv[j].x + qa[i].y * kv[j].y
                              + qa[i].z * kv[j].z + qa[i].w * kv[j].w;
#pragma unroll
            for (int i = 0; i < 4; i++) qa[i] = *(float4*)&q2s[(4 * ty + i) * 68 + 4 * d4];
#pragma unroll
            for (int j = 0; j < 4; j++) kv[j] = *(float4*)&k2s[(4 * tx + j) * 68 + 4 * d4];
#pragma unroll
            for (int i = 0; i < 4; i++)
#pragma unroll
                for (int j = 0; j < 4; j++)
                    s2[i][j] += qa[i].x * kv[j].x + qa[i].y * kv[j].y
                              + qa[i].z * kv[j].z + qa[i].w * kv[j].w;
        }

        float mav[4];
#pragma unroll
        for (int j = 0; j < 4; j++) mav[j] = madd[4 * tx + j];

        // ---- Dual online softmax (row stats reduced over 16-lane groups) ----
#pragma unroll
        for (int i = 0; i < 4; i++) {
#pragma unroll
            for (int j = 0; j < 4; j++) { s1[i][j] += mav[j]; s2[i][j] += mav[j]; }

            // stream 1
            float mx = fmaxf(fmaxf(s1[i][0], s1[i][1]), fmaxf(s1[i][2], s1[i][3]));
#pragma unroll
            for (int sft = 1; sft < 16; sft <<= 1)
                mx = fmaxf(mx, __shfl_xor_sync(0xffffffffu, mx, sft));
            float nm = fmaxf(m1[i], mx);
            float e0 = __expf(s1[i][0] - nm), e1 = __expf(s1[i][1] - nm);
            float e2 = __expf(s1[i][2] - nm), e3 = __expf(s1[i][3] - nm);
            float ls = e0 + e1 + e2 + e3;
#pragma unroll
            for (int sft = 1; sft < 16; sft <<= 1)
                ls += __shfl_xor_sync(0xffffffffu, ls, sft);
            float alpha = __expf(m1[i] - nm);
            l1[i] = l1[i] * alpha + ls;
            m1[i] = nm;
#pragma unroll
            for (int j = 0; j < 8; j++) o1[i][j] *= alpha;
            p1s[(4 * ty + i) * 68 + 4 * tx + 0] = e0;
            p1s[(4 * ty + i) * 68 + 4 * tx + 1] = e1;
            p1s[(4 * ty + i) * 68 + 4 * tx + 2] = e2;
            p1s[(4 * ty + i) * 68 + 4 * tx + 3] = e3;

            // stream 2
            mx = fmaxf(fmaxf(s2[i][0], s2[i][1]), fmaxf(s2[i][2], s2[i][3]));
#pragma unroll
            for (int sft = 1; sft < 16; sft <<= 1)
                mx = fmaxf(mx, __shfl_xor_sync(0xffffffffu, mx, sft));
            nm = fmaxf(m2[i], mx);
            e0 = __expf(s2[i][0] - nm); e1 = __expf(s2[i][1] - nm);
            e2 = __expf(s2[i][2] - nm); e3 = __expf(s2[i][3] - nm);
            ls = e0 + e1 + e2 + e3;
#pragma unroll
            for (int sft = 1; sft < 16; sft <<= 1)
                ls += __shfl_xor_sync(0xffffffffu, ls, sft);
            alpha = __expf(m2[i] - nm);
            l2[i] = l2[i] * alpha + ls;
            m2[i] = nm;
#pragma unroll
            for (int j = 0; j < 8; j++) o2[i][j] *= alpha;
            p2s[(4 * ty + i) * 68 + 4 * tx + 0] = e0;
            p2s[(4 * ty + i) * 68 + 4 * tx + 1] = e1;
            p2s[(4 * ty + i) * 68 + 4 * tx + 2] = e2;
            p2s[(4 * ty + i) * 68 + 4 * tx + 3] = e3;
        }
        __syncthreads();

        // ---- PV (register-tiled, dual stream, shared v reads) ----
#pragma unroll 4
        for (int k = 0; k < 64; k++) {
            float4 vb0 = *(float4*)&vs[k * 128 + 8 * tx];
            float4 vb1 = *(float4*)&vs[k * 128 + 8 * tx + 4];
#pragma unroll
            for (int i = 0; i < 4; i++) {
                float pa1 = p1s[(4 * ty + i) * 68 + k];
                float pa2 = p2s[(4 * ty + i) * 68 + k];
                o1[i][0] += pa1 * vb0.x; o1[i][1] += pa1 * vb0.y;
                o1[i][2] += pa1 * vb0.z; o1[i][3] += pa1 * vb0.w;
                o1[i][4] += pa1 * vb1.x; o1[i][5] += pa1 * vb1.y;
                o1[i][6] += pa1 * vb1.z; o1[i][7] += pa1 * vb1.w;
                o2[i][0] += pa2 * vb0.x; o2[i][1] += pa2 * vb0.y;
                o2[i][2] += pa2 * vb0.z; o2[i][3] += pa2 * vb0.w;
                o2[i][4] += pa2 * vb1.x; o2[i][5] += pa2 * vb1.y;
                o2[i][6] += pa2 * vb1.z; o2[i][7] += pa2 * vb1.w;
            }
        }
    }

    // Epilogue: out = softmax1@v / l1 - lam * softmax2@v / l2
#pragma unroll
    for (int i = 0; i < 4; i++) {
        const float inv1 = 1.0f / l1[i];
        const float inv2 = lam / l2[i];
        const size_t row = (size_t)b * S_LEN + q0 + 4 * ty + i;
        float* op = out + row * DMODEL + h * 128 + 8 * tx;
        float4 w0, w1;
        w0.x = o1[i][0] * inv1 - o2[i][0] * inv2;
        w0.y = o1[i][1] * inv1 - o2[i][1] * inv2;
        w0.z = o1[i][2] * inv1 - o2[i][2] * inv2;
        w0.w = o1[i][3] * inv1 - o2[i][3] * inv2;
        w1.x = o1[i][4] * inv1 - o2[i][4] * inv2;
        w1.y = o1[i][5] * inv1 - o2[i][5] * inv2;
        w1.z = o1[i][6] * inv1 - o2[i][6] * inv2;
        w1.w = o1[i][7] * inv1 - o2[i][7] * inv2;
        *(float4*)op = w0;
        *(float4*)(op + 4) = w1;
    }
}

// ---------------------------------------------------------------------------
extern "C" void kernel_launch(void* const* d_in, const int* in_sizes, int n_in,
                              void* d_out, int out_size)
{
    const float* hidden = (const float*)d_in[0];
    const float* amask  = (const float*)d_in[1];
    const float* W_attn = (const float*)d_in[2];
    const float* b_attn = (const float*)d_in[3];
    const float* W_proj = (const float*)d_in[4];
    const float* b_proj = (const float*)d_in[5];
    const float* lam    = (const float*)d_in[6];
    float* out = (float*)d_out;

    void* qkv_p = nullptr;
    void* attn_p = nullptr;
    cudaGetSymbolAddress(&qkv_p, g_qkv);
    cudaGetSymbolAddress(&attn_p, g_attn);
    float* qkv  = (float*)qkv_p;
    float* attn = (float*)attn_p;

    cudaFuncSetAttribute(diff_attn_kernel,
                         cudaFuncAttributeMaxDynamicSharedMemorySize, ATT_SMEM_BYTES);

    dim3 g1(N_QKV / 128, M_TOK / 128);      // (48, 32)
    sgemm_bias_kernel<<<g1, 256>>>(hidden, W_attn, b_attn, qkv, M_TOK, N_QKV, DMODEL);

    dim3 g2(S_LEN / 64, B_SZ * NHEAD);      // (32, 32)
    diff_attn_kernel<<<g2, 256, ATT_SMEM_BYTES>>>(qkv, amask, lam, attn);

    dim3 g3(DMODEL / 128, M_TOK / 128);     // (16, 32)
    sgemm_bias_kernel<<<g3, 256>>>(attn, W_proj, b_proj, out, M_TOK, DMODEL, DMODEL);
}

// round 3
// speedup vs baseline: 1.4527x; 1.4527x over previous
#include <cuda_runtime.h>
#include <cuda_bf16.h>
#include <cuda.h>
#include <cstdint>

// Problem dims (fixed by setup_inputs)
#define B_SZ   2
#define S_LEN  2048
#define DMODEL 2048
#define NHEAD  16
#define M_TOK  (B_SZ * S_LEN)     // 4096
#define N_QKV  (3 * DMODEL)       // 6144
#define KDIM   DMODEL             // 2048

// ---------------- scratch (static device globals: allocation-free) ----------
__device__ float g_qkv[(size_t)M_TOK * N_QKV];
__device__ float g_attn[(size_t)M_TOK * DMODEL];
__device__ unsigned short g_Ah[(size_t)M_TOK * KDIM];
__device__ unsigned short g_Al[(size_t)M_TOK * KDIM];
__device__ unsigned short g_WAh[(size_t)N_QKV * KDIM];
__device__ unsigned short g_WAl[(size_t)N_QKV * KDIM];
__device__ unsigned short g_WPh[(size_t)DMODEL * KDIM];
__device__ unsigned short g_WPl[(size_t)DMODEL * KDIM];
__device__ unsigned short g_Oh[(size_t)M_TOK * KDIM];
__device__ unsigned short g_Ol[(size_t)M_TOK * KDIM];

// ---------------------------------------------------------------------------
// PTX helpers (base sm_90 features only — NO 'a'-gated instructions)
// ---------------------------------------------------------------------------
__device__ __forceinline__ uint32_t smem_u32(const void* p) {
    uint32_t a;
    asm("{ .reg .u64 t; cvta.to.shared.u64 t, %1; cvt.u32.u64 %0, t; }" : "=r"(a) : "l"(p));
    return a;
}

#define MBARRIER_INIT(addr, cnt) \
    asm volatile("mbarrier.init.shared.b64 [%0], %1;" :: "r"((uint32_t)(addr)), "r"((uint32_t)(cnt)) : "memory")

#define MBARRIER_ARRIVE(addr) \
    asm volatile("mbarrier.arrive.shared.b64 _, [%0];" :: "r"((uint32_t)(addr)) : "memory")

#define MBARRIER_EXPECT_TX(addr, bytes) \
    asm volatile("mbarrier.arrive.expect_tx.shared.b64 _, [%0], %1;" :: "r"((uint32_t)(addr)), "r"((uint32_t)(bytes)) : "memory")

#define MBARRIER_WAIT_PARITY(mbar_smem_addr, phase_parity) do { \
    uint32_t _mbar = (uint32_t)(mbar_smem_addr); \
    uint32_t _parity = (uint32_t)(phase_parity); \
    uint32_t _done; \
    asm volatile( \
        "{\n\t.reg .pred p;\n\t" \
        "mbarrier.try_wait.parity.acquire.cta.shared::cta.b64 p, [%1], %2;\n\t" \
        "selp.b32 %0, 1, 0, p;\n\t}" \
        : "=r"(_done) : "r"(_mbar), "r"(_parity) : "memory"); \
    if (!_done) { \
        asm volatile( \
            "{\n\t.reg .pred P1;\n\t" \
            "WAIT_LOOP_%=:\n\t" \
            "mbarrier.try_wait.parity.acquire.cta.shared::cta.b64 P1, [%0], %1, 0x989680;\n\t" \
            "@P1 bra.uni WAIT_DONE_%=;\n\t" \
            "bra.uni WAIT_LOOP_%=;\n\t" \
            "WAIT_DONE_%=:\n\t}" \
            :: "r"(_mbar), "r"(_parity) : "memory"); \
    } \
} while(0)

#define MBARRIER_WAIT_PARITY_RELAXED(mbar_smem_addr, phase_parity) do { \
    uint32_t _mbar = (uint32_t)(mbar_smem_addr); \
    uint32_t _parity = (uint32_t)(phase_parity); \
    uint32_t _done; \
    asm volatile( \
        "{\n\t.reg .pred p;\n\t" \
        "mbarrier.try_wait.parity.relaxed.cta.shared::cta.b64 p, [%1], %2, 0x989680;\n\t" \
        "selp.b32 %0, 1, 0, p;\n\t}" \
        : "=r"(_done) : "r"(_mbar), "r"(_parity) : "memory"); \
    if (!_done) { \
        asm volatile( \
            "{\n\t.reg .pred P1;\n\t" \
            "WAIT_LOOP_%=:\n\t" \
            "mbarrier.try_wait.parity.relaxed.cta.shared::cta.b64 P1, [%0], %1, 0x989680;\n\t" \
            "@P1 bra.uni WAIT_DONE_%=;\n\t" \
            "bra.uni WAIT_LOOP_%=;\n\t" \
            "WAIT_DONE_%=:\n\t}" \
            :: "r"(_mbar), "r"(_parity) : "memory"); \
    } \
} while(0)

__device__ __forceinline__ void tma2d(uint32_t dst, const void* map, int x, int y, uint32_t mbar) {
    asm volatile(
        "cp.async.bulk.tensor.2d.shared::cta.global.tile.mbarrier::complete_tx::bytes "
        "[%0], [%1, {%2, %3}], [%4];"
        :: "r"(dst), "l"(map), "r"(x), "r"(y), "r"(mbar) : "memory");
}

__device__ __forceinline__ void ldsm4(uint32_t* r, uint32_t addr) {
    asm volatile("ldmatrix.sync.aligned.m8n8.x4.shared.b16 {%0,%1,%2,%3}, [%4];"
                 : "=r"(r[0]), "=r"(r[1]), "=r"(r[2]), "=r"(r[3]) : "r"(addr));
}

__device__ __forceinline__ void mma_bf16(float* d, const uint32_t* a, uint32_t b0, uint32_t b1) {
    asm volatile(
        "mma.sync.aligned.m16n8k16.row.col.f32.bf16.bf16.f32 "
        "{%0,%1,%2,%3}, {%4,%5,%6,%7}, {%8,%9}, {%0,%1,%2,%3};"
        : "+f"(d[0]), "+f"(d[1]), "+f"(d[2]), "+f"(d[3])
        : "r"(a[0]), "r"(a[1]), "r"(a[2]), "r"(a[3]), "r"(b0), "r"(b1));
}

// ---------------------------------------------------------------------------
// bf16x3 GEMM:  C[M,N] = A[M,K] @ B[N,K]^T + bias   (fp32 out)
// A,B: (hi, lo) bf16 pairs, K-major rows. CTA 128x128, K-chunk 64, 3-stage TMA.
// 8 warps = 4(M) x 2(N); warp tile 32x64; mma.sync m16n8k16 bf16.
// ---------------------------------------------------------------------------
#define GSTAGES     3
#define GCHUNKS     32                     // K=2048 / 64
#define GTILE_BYTES 16384                  // 128 rows x 64 bf16 (128B)
#define GSTAGE_BYTES (4 * GTILE_BYTES)     // Ah, Al, Bh, Bl
#define GSM_DATA    1024
#define GEMM_SMEM   (GSM_DATA + GSTAGES * GSTAGE_BYTES)   // 197632

__global__ __launch_bounds__(256, 1)
void gemm_bf16x3_kernel(const __grid_constant__ CUtensorMap tmAh,
                        const __grid_constant__ CUtensorMap tmAl,
                        const __grid_constant__ CUtensorMap tmBh,
                        const __grid_constant__ CUtensorMap tmBl,
                        const float* __restrict__ bias,
                        float* __restrict__ C, int N)
{
    extern __shared__ __align__(1024) char gsm[];
    const uint32_t sb = smem_u32(gsm);
    const int tid = threadIdx.x;
    const int lane = tid & 31;
    const int wid = tid >> 5;
    const int row0 = blockIdx.y * 128;
    const int col0 = blockIdx.x * 128;
    const int wm = (wid & 3) * 32;         // warp M offset in tile
    const int wn = (wid >> 2) * 64;        // warp N offset in tile

    // mbarriers: full[s] at sb+8s (count 1, tx), empty[s] at sb+24+8s (count 256)
    if (tid == 0) {
#pragma unroll
        for (int s = 0; s < GSTAGES; ++s) {
            MBARRIER_INIT(sb + 8 * s, 1);
            MBARRIER_INIT(sb + 24 + 8 * s, 256);
        }
    }
    __syncthreads();

    // Pre-issue chunks 0..2
    if (tid == 0) {
#pragma unroll
        for (int p = 0; p < GSTAGES; ++p) {
            const uint32_t st = sb + GSM_DATA + p * GSTAGE_BYTES;
            MBARRIER_EXPECT_TX(sb + 8 * p, GSTAGE_BYTES);
            const int k0 = p * 64;
            tma2d(st,                  &tmAh, k0, row0, sb + 8 * p);
            tma2d(st + GTILE_BYTES,    &tmAl, k0, row0, sb + 8 * p);
            tma2d(st + 2 * GTILE_BYTES,&tmBh, k0, col0, sb + 8 * p);
            tma2d(st + 3 * GTILE_BYTES,&tmBl, k0, col0, sb + 8 * p);
        }
    }

    float acc[2][8][4];
#pragma unroll
    for (int i = 0; i < 2; i++)
#pragma unroll
        for (int j = 0; j < 8; j++)
#pragma unroll
            for (int k = 0; k < 4; k++) acc[i][j][k] = 0.f;

    // Precompute per-thread ldmatrix bases (SW128 swizzle: mask is row-constant)
    // addr(row, colbyte) = tilebase + row*128 + (colbyte ^ ((row&7)<<4))
    const uint32_t cbase = (lane >> 4) * 16;    // 8-element half select (bytes)
    uint32_t aRB[2], aMask[2], bRB[4], bMask[4];
#pragma unroll
    for (int mt = 0; mt < 2; ++mt) {
        const int r = wm + mt * 16 + (lane & 15);
        aRB[mt] = (uint32_t)r * 128;
        aMask[mt] = (uint32_t)((r & 7) << 4);
    }
#pragma unroll
    for (int j = 0; j < 4; ++j) {
        const int r = wn + j * 16 + (lane & 15);
        bRB[j] = (uint32_t)r * 128;
        bMask[j] = (uint32_t)((r & 7) << 4);
    }

    for (int c = 0; c < GCHUNKS; ++c) {
        const int u = c / 3;
        const int s = c - u * 3;
        MBARRIER_WAIT_PARITY(sb + 8 * s, (uint32_t)(u & 1));

        const uint32_t stA  = sb + GSM_DATA + s * GSTAGE_BYTES;
        const uint32_t stAl = stA + GTILE_BYTES;
        const uint32_t stB  = stA + 2 * GTILE_BYTES;
        const uint32_t stBl = stA + 3 * GTILE_BYTES;

#pragma unroll
        for (int kk = 0; kk < 4; ++kk) {
            const uint32_t kb = cbase + kk * 32;   // column bytes within 128B row
            uint32_t ah[2][4], al[2][4], bh[4][4], bl[4][4];
#pragma unroll
            for (int mt = 0; mt < 2; ++mt) {
                ldsm4(ah[mt], stA  + aRB[mt] + (kb ^ aMask[mt]));
                ldsm4(al[mt], stAl + aRB[mt] + (kb ^ aMask[mt]));
            }
#pragma unroll
            for (int j = 0; j < 4; ++j) {
                ldsm4(bh[j], stB  + bRB[j] + (kb ^ bMask[j]));
                ldsm4(bl[j], stBl + bRB[j] + (kb ^ bMask[j]));
            }
#pragma unroll
            for (int mt = 0; mt < 2; ++mt) {
#pragma unroll
                for (int j = 0; j < 4; ++j) {
                    // x4 ldmatrix covers two n8 tiles: tile 2j = regs {0,2}, tile 2j+1 = {1,3}
                    mma_bf16(acc[mt][2 * j],     ah[mt], bh[j][0], bh[j][2]);
                    mma_bf16(acc[mt][2 * j],     ah[mt], bl[j][0], bl[j][2]);
                    mma_bf16(acc[mt][2 * j],     al[mt], bh[j][0], bh[j][2]);
                    mma_bf16(acc[mt][2 * j + 1], ah[mt], bh[j][1], bh[j][3]);
                    mma_bf16(acc[mt][2 * j + 1], ah[mt], bl[j][1], bl[j][3]);
                    mma_bf16(acc[mt][2 * j + 1], al[mt], bh[j][1], bh[j][3]);
                }
            }
        }

        MBARRIER_ARRIVE(sb + 24 + 8 * s);

        const int p = c + GSTAGES;
        if (tid == 0 && p < GCHUNKS) {
            const int up = p / 3;
            MBARRIER_WAIT_PARITY_RELAXED(sb + 24 + 8 * s, (uint32_t)((up & 1) ^ 1));
            const uint32_t st = sb + GSM_DATA + s * GSTAGE_BYTES;
            MBARRIER_EXPECT_TX(sb + 8 * s, GSTAGE_BYTES);
            const int k0 = p * 64;
            tma2d(st,                   &tmAh, k0, row0, sb + 8 * s);
            tma2d(st + GTILE_BYTES,     &tmAl, k0, row0, sb + 8 * s);
            tma2d(st + 2 * GTILE_BYTES, &tmBh, k0, col0, sb + 8 * s);
            tma2d(st + 3 * GTILE_BYTES, &tmBl, k0, col0, sb + 8 * s);
        }
    }

    // Epilogue: bias add + store (mma d-frag mapping)
    const int rr = lane >> 2;
    const int cc = (lane & 3) * 2;
#pragma unroll
    for (int mt = 0; mt < 2; ++mt) {
        const int mrow = row0 + wm + mt * 16 + rr;
#pragma unroll
        for (int nt = 0; nt < 8; ++nt) {
            const int n = col0 + wn + nt * 8 + cc;
            const float2 bb = *(const float2*)(bias + n);
            float2 v0, v1;
            v0.x = acc[mt][nt][0] + bb.x; v0.y = acc[mt][nt][1] + bb.y;
            v1.x = acc[mt][nt][2] + bb.x; v1.y = acc[mt][nt][3] + bb.y;
            *(float2*)(C + (size_t)mrow * N + n) = v0;
            *(float2*)(C + (size_t)(mrow + 8) * N + n) = v1;
        }
    }
}

// ---------------------------------------------------------------------------
// fp32 -> (hi, lo) bf16 split, elementwise
// ---------------------------------------------------------------------------
__global__ __launch_bounds__(256)
void split_kernel(const float4* __restrict__ x, uint2* __restrict__ hi,
                  uint2* __restrict__ lo, int n4)
{
    int i = blockIdx.x * blockDim.x + threadIdx.x;
    if (i >= n4) return;
    float4 v = x[i];
    __nv_bfloat16 h0 = __float2bfloat16(v.x), h1 = __float2bfloat16(v.y);
    __nv_bfloat16 h2 = __float2bfloat16(v.z), h3 = __float2bfloat16(v.w);
    __nv_bfloat16 l0 = __float2bfloat16(v.x - __bfloat162float(h0));
    __nv_bfloat16 l1 = __float2bfloat16(v.y - __bfloat162float(h1));
    __nv_bfloat16 l2 = __float2bfloat16(v.z - __bfloat162float(h2));
    __nv_bfloat16 l3 = __float2bfloat16(v.w - __bfloat162float(h3));
    uint2 H, L;
    H.x = ((uint32_t)__bfloat16_as_ushort(h1) << 16) | __bfloat16_as_ushort(h0);
    H.y = ((uint32_t)__bfloat16_as_ushort(h3) << 16) | __bfloat16_as_ushort(h2);
    L.x = ((uint32_t)__bfloat16_as_ushort(l1) << 16) | __bfloat16_as_ushort(l0);
    L.y = ((uint32_t)__bfloat16_as_ushort(l3) << 16) | __bfloat16_as_ushort(l2);
    hi[i] = H;
    lo[i] = L;
}

// fp32 W[K][N] -> transposed bf16 split hiT[N][K], loT[N][K]
__global__ __launch_bounds__(256)
void splitT_kernel(const float* __restrict__ W, __nv_bfloat16* __restrict__ hiT,
                   __nv_bfloat16* __restrict__ loT, int K, int N)
{
    __shared__ float t[32][33];
    const int tx = threadIdx.x, ty = threadIdx.y;     // 32 x 8
    const int n0 = blockIdx.x * 32, k0 = blockIdx.y * 32;
#pragma unroll
    for (int r = 0; r < 4; ++r)
        t[ty + 8 * r][tx] = W[(size_t)(k0 + ty + 8 * r) * N + n0 + tx];
    __syncthreads();
#pragma unroll
    for (int r = 0; r < 4; ++r) {
        const int nn = ty + 8 * r;
        float v = t[tx][nn];
        __nv_bfloat16 h = __float2bfloat16(v);
        __nv_bfloat16 l = __float2bfloat16(v - __bfloat162float(h));
        const size_t o = (size_t)(n0 + nn) * K + k0 + tx;
        hiT[o] = h;
        loT[o] = l;
    }
}

// ---------------------------------------------------------------------------
// Flash differential attention (fp32, unchanged — proven correct in R1)
// ---------------------------------------------------------------------------
#define ATT_SMEM_FLOATS (6 * 64 * 68 + 64 * 128 + 64)
#define ATT_SMEM_BYTES  (ATT_SMEM_FLOATS * 4)

__global__ __launch_bounds__(256, 1)
void diff_attn_kernel(const float* __restrict__ qkv, const float* __restrict__ amask,
                      const float* __restrict__ lambda_p, float* __restrict__ out)
{
    extern __shared__ __align__(16) float sm[];
    float* q1s  = sm;
    float* q2s  = q1s + 64 * 68;
    float* k1s  = q2s + 64 * 68;
    float* k2s  = k1s + 64 * 68;
    float* vs   = k2s + 64 * 68;
    float* p1s  = vs + 64 * 128;
    float* p2s  = p1s + 64 * 68;
    float* madd = p2s + 64 * 68;

    const int tid = threadIdx.x;
    const int tx = tid & 15, ty = tid >> 4;
    const int q0 = blockIdx.x * 64;
    const int bh = blockIdx.y;
    const int b = bh >> 4, h = bh & 15;
    const float scale = 0.0883883476483184f;
    const float lam = *lambda_p;

    const float* base = qkv + (size_t)b * S_LEN * N_QKV;
    const float* q1g = base + h * 64;
    const float* q2g = base + 1024 + h * 64;
    const float* k1g = base + 2048 + h * 64;
    const float* k2g = base + 3072 + h * 64;
    const float* vg  = base + 4096 + h * 128;

#pragma unroll
    for (int r = 0; r < 4; r++) {
        int id = tid + r * 256;
        int qi = id >> 4, c4 = (id & 15) * 4;
        float4 v1 = *(const float4*)(q1g + (size_t)(q0 + qi) * N_QKV + c4);
        float4 v2 = *(const float4*)(q2g + (size_t)(q0 + qi) * N_QKV + c4);
        v1.x *= scale; v1.y *= scale; v1.z *= scale; v1.w *= scale;
        v2.x *= scale; v2.y *= scale; v2.z *= scale; v2.w *= scale;
        *(float4*)&q1s[qi * 68 + c4] = v1;
        *(float4*)&q2s[qi * 68 + c4] = v2;
    }

    float o1[4][8], o2[4][8];
    float m1[4], l1[4], m2[4], l2[4];
#pragma unroll
    for (int i = 0; i < 4; i++) {
        m1[i] = -1e30f; l1[i] = 0.f; m2[i] = -1e30f; l2[i] = 0.f;
#pragma unroll
        for (int j = 0; j < 8; j++) { o1[i][j] = 0.f; o2[i][j] = 0.f; }
    }

    for (int kb = 0; kb < S_LEN / 64; ++kb) {
        __syncthreads();
        const int k0 = kb * 64;
#pragma unroll
        for (int r = 0; r < 4; r++) {
            int id = tid + r * 256;
            int ki = id >> 4, c4 = (id & 15) * 4;
            *(float4*)&k1s[ki * 68 + c4] = *(const float4*)(k1g + (size_t)(k0 + ki) * N_QKV + c4);
            *(float4*)&k2s[ki * 68 + c4] = *(const float4*)(k2g + (size_t)(k0 + ki) * N_QKV + c4);
        }
#pragma unroll
        for (int r = 0; r < 8; r++) {
            int id = tid + r * 256;
            int ki = id >> 5, c4 = (id & 31) * 4;
            *(float4*)&vs[ki * 128 + c4] = *(const float4*)(vg + (size_t)(k0 + ki) * N_QKV + c4);
        }
        if (tid < 64)
            madd[tid] = (1.0f - amask[(size_t)b * S_LEN + k0 + tid]) * -10000.0f;
        __syncthreads();

        float s1[4][4], s2[4][4];
#pragma unroll
        for (int i = 0; i < 4; i++)
#pragma unroll
            for (int j = 0; j < 4; j++) { s1[i][j] = 0.f; s2[i][j] = 0.f; }

#pragma unroll 4
        for (int d4 = 0; d4 < 16; ++d4) {
            float4 qa[4], kv[4];
#pragma unroll
            for (int i = 0; i < 4; i++) qa[i] = *(float4*)&q1s[(4 * ty + i) * 68 + 4 * d4];
#pragma unroll
            for (int j = 0; j < 4; j++) kv[j] = *(float4*)&k1s[(4 * tx + j) * 68 + 4 * d4];
#pragma unroll
            for (int i = 0; i < 4; i++)
#pragma unroll
                for (int j = 0; j < 4; j++)
                    s1[i][j] += qa[i].x * kv[j].x + qa[i].y * kv[j].y
                              + qa[i].z * kv[j].z + qa[i].w * kv[j].w;
#pragma unroll
            for (int i = 0; i < 4; i++) qa[i] = *(float4*)&q2s[(4 * ty + i) * 68 + 4 * d4];
#pragma unroll
            for (int j = 0; j < 4; j++) kv[j] = *(float4*)&k2s[(4 * tx + j) * 68 + 4 * d4];
#pragma unroll
            for (int i = 0; i < 4; i++)
#pragma unroll
                for (int j = 0; j < 4; j++)
                    s2[i][j] += qa[i].x * kv[j].x + qa[i].y * kv[j].y
                              + qa[i].z * kv[j].z + qa[i].w * kv[j].w;
        }

        float mav[4];
#pragma unroll
        for (int j = 0; j < 4; j++) mav[j] = madd[4 * tx + j];

#pragma unroll
        for (int i = 0; i < 4; i++) {
#pragma unroll
            for (int j = 0; j < 4; j++) { s1[i][j] += mav[j]; s2[i][j] += mav[j]; }

            float mx = fmaxf(fmaxf(s1[i][0], s1[i][1]), fmaxf(s1[i][2], s1[i][3]));
#pragma unroll
            for (int sft = 1; sft < 16; sft <<= 1)
                mx = fmaxf(mx, __shfl_xor_sync(0xffffffffu, mx, sft));
            float nm = fmaxf(m1[i], mx);
            float e0 = __expf(s1[i][0] - nm), e1 = __expf(s1[i][1] - nm);
            float e2 = __expf(s1[i][2] - nm), e3 = __expf(s1[i][3] - nm);
            float ls = e0 + e1 + e2 + e3;
#pragma unroll
            for (int sft = 1; sft < 16; sft <<= 1)
                ls += __shfl_xor_sync(0xffffffffu, ls, sft);
            float alpha = __expf(m1[i] - nm);
            l1[i] = l1[i] * alpha + ls;
            m1[i] = nm;
#pragma unroll
            for (int j = 0; j < 8; j++) o1[i][j] *= alpha;
            p1s[(4 * ty + i) * 68 + 4 * tx + 0] = e0;
            p1s[(4 * ty + i) * 68 + 4 * tx + 1] = e1;
            p1s[(4 * ty + i) * 68 + 4 * tx + 2] = e2;
            p1s[(4 * ty + i) * 68 + 4 * tx + 3] = e3;

            mx = fmaxf(fmaxf(s2[i][0], s2[i][1]), fmaxf(s2[i][2], s2[i][3]));
#pragma unroll
            for (int sft = 1; sft < 16; sft <<= 1)
                mx = fmaxf(mx, __shfl_xor_sync(0xffffffffu, mx, sft));
            nm = fmaxf(m2[i], mx);
            e0 = __expf(s2[i][0] - nm); e1 = __expf(s2[i][1] - nm);
            e2 = __expf(s2[i][2] - nm); e3 = __expf(s2[i][3] - nm);
            ls = e0 + e1 + e2 + e3;
#pragma unroll
            for (int sft = 1; sft < 16; sft <<= 1)
                ls += __shfl_xor_sync(0xffffffffu, ls, sft);
            alpha = __expf(m2[i] - nm);
            l2[i] = l2[i] * alpha + ls;
            m2[i] = nm;
#pragma unroll
            for (int j = 0; j < 8; j++) o2[i][j] *= alpha;
            p2s[(4 * ty + i) * 68 + 4 * tx + 0] = e0;
            p2s[(4 * ty + i) * 68 + 4 * tx + 1] = e1;
            p2s[(4 * ty + i) * 68 + 4 * tx + 2] = e2;
            p2s[(4 * ty + i) * 68 + 4 * tx + 3] = e3;
        }
        __syncthreads();

#pragma unroll 4
        for (int k = 0; k < 64; k++) {
            float4 vb0 = *(float4*)&vs[k * 128 + 8 * tx];
            float4 vb1 = *(float4*)&vs[k * 128 + 8 * tx + 4];
#pragma unroll
            for (int i = 0; i < 4; i++) {
                float pa1 = p1s[(4 * ty + i) * 68 + k];
                float pa2 = p2s[(4 * ty + i) * 68 + k];
                o1[i][0] += pa1 * vb0.x; o1[i][1] += pa1 * vb0.y;
                o1[i][2] += pa1 * vb0.z; o1[i][3] += pa1 * vb0.w;
                o1[i][4] += pa1 * vb1.x; o1[i][5] += pa1 * vb1.y;
                o1[i][6] += pa1 * vb1.z; o1[i][7] += pa1 * vb1.w;
                o2[i][0] += pa2 * vb0.x; o2[i][1] += pa2 * vb0.y;
                o2[i][2] += pa2 * vb0.z; o2[i][3] += pa2 * vb0.w;
                o2[i][4] += pa2 * vb1.x; o2[i][5] += pa2 * vb1.y;
                o2[i][6] += pa2 * vb1.z; o2[i][7] += pa2 * vb1.w;
            }
        }
    }

#pragma unroll
    for (int i = 0; i < 4; i++) {
        const float inv1 = 1.0f / l1[i];
        const float inv2 = lam / l2[i];
        const size_t row = (size_t)b * S_LEN + q0 + 4 * ty + i;
        float* op = out + row * DMODEL + h * 128 + 8 * tx;
        float4 w0, w1;
        w0.x = o1[i][0] * inv1 - o2[i][0] * inv2;
        w0.y = o1[i][1] * inv1 - o2[i][1] * inv2;
        w0.z = o1[i][2] * inv1 - o2[i][2] * inv2;
        w0.w = o1[i][3] * inv1 - o2[i][3] * inv2;
        w1.x = o1[i][4] * inv1 - o2[i][4] * inv2;
        w1.y = o1[i][5] * inv1 - o2[i][5] * inv2;
        w1.z = o1[i][6] * inv1 - o2[i][6] * inv2;
        w1.w = o1[i][7] * inv1 - o2[i][7] * inv2;
        *(float4*)op = w0;
        *(float4*)(op + 4) = w1;
    }
}

// ---------------------------------------------------------------------------
// Host side
// ---------------------------------------------------------------------------
typedef CUresult (*PFN_tmEncode)(
    CUtensorMap*, CUtensorMapDataType, cuuint32_t, void*,
    const cuuint64_t*, const cuuint64_t*, const cuuint32_t*, const cuuint32_t*,
    CUtensorMapInterleave, CUtensorMapSwizzle, CUtensorMapL2promotion,
    CUtensorMapFloatOOBfill);

static void make_map(PFN_tmEncode fn, CUtensorMap* m, void* ptr,
                     unsigned long long rows)
{
    cuuint64_t dims[2]    = {(cuuint64_t)KDIM, (cuuint64_t)rows};
    cuuint64_t strides[1] = {(cuuint64_t)KDIM * 2};
    cuuint32_t box[2]     = {64u, 128u};      // 64 bf16 = 128B (SW128 atom)
    cuuint32_t es[2]      = {1u, 1u};
    fn(m, CU_TENSOR_MAP_DATA_TYPE_BFLOAT16, 2, ptr, dims, strides, box, es,
       CU_TENSOR_MAP_INTERLEAVE_NONE, CU_TENSOR_MAP_SWIZZLE_128B,
       CU_TENSOR_MAP_L2_PROMOTION_L2_128B, CU_TENSOR_MAP_FLOAT_OOB_FILL_NONE);
}

extern "C" void kernel_launch(void* const* d_in, const int* in_sizes, int n_in,
                              void* d_out, int out_size)
{
    const float* hidden = (const float*)d_in[0];
    const float* amask  = (const float*)d_in[1];
    const float* W_attn = (const float*)d_in[2];
    const float* b_attn = (const float*)d_in[3];
    const float* W_proj = (const float*)d_in[4];
    const float* b_proj = (const float*)d_in[5];
    const float* lam    = (const float*)d_in[6];
    float* out = (float*)d_out;

    void *qkv_p, *attn_p, *Ah, *Al, *WAh, *WAl, *WPh, *WPl, *Oh, *Ol;
    cudaGetSymbolAddress(&qkv_p, g_qkv);
    cudaGetSymbolAddress(&attn_p, g_attn);
    cudaGetSymbolAddress(&Ah, g_Ah);   cudaGetSymbolAddress(&Al, g_Al);
    cudaGetSymbolAddress(&WAh, g_WAh); cudaGetSymbolAddress(&WAl, g_WAl);
    cudaGetSymbolAddress(&WPh, g_WPh); cudaGetSymbolAddress(&WPl, g_WPl);
    cudaGetSymbolAddress(&Oh, g_Oh);   cudaGetSymbolAddress(&Ol, g_Ol);
    float* qkv  = (float*)qkv_p;
    float* attn = (float*)attn_p;

    // tensormap encoder via runtime driver-entry-point (no -lcuda needed)
    void* fnp = nullptr;
    cudaDriverEntryPointQueryResult qres;
    cudaGetDriverEntryPointByVersion("cuTensorMapEncodeTiled", &fnp, 12000,
                                     cudaEnableDefault, &qres);
    PFN_tmEncode enc = (PFN_tmEncode)fnp;

    CUtensorMap tAh, tAl, tWAh, tWAl, tWPh, tWPl, tOh, tOl;
    make_map(enc, &tAh,  Ah,  M_TOK);
    make_map(enc, &tAl,  Al,  M_TOK);
    make_map(enc, &tWAh, WAh, N_QKV);
    make_map(enc, &tWAl, WAl, N_QKV);
    make_map(enc, &tWPh, WPh, DMODEL);
    make_map(enc, &tWPl, WPl, DMODEL);
    make_map(enc, &tOh,  Oh,  M_TOK);
    make_map(enc, &tOl,  Ol,  M_TOK);

    cudaFuncSetAttribute(diff_attn_kernel,
                         cudaFuncAttributeMaxDynamicSharedMemorySize, ATT_SMEM_BYTES);
    cudaFuncSetAttribute(gemm_bf16x3_kernel,
                         cudaFuncAttributeMaxDynamicSharedMemorySize, GEMM_SMEM);

    // 1) split hidden -> Ah/Al
    {
        int n4 = (M_TOK * KDIM) / 4;
        split_kernel<<<n4 / 256, 256>>>((const float4*)hidden, (uint2*)Ah, (uint2*)Al, n4);
    }
    // 2) split+transpose weights
    {
        dim3 g(N_QKV / 32, KDIM / 32);
        splitT_kernel<<<g, dim3(32, 8)>>>(W_attn, (__nv_bfloat16*)WAh, (__nv_bfloat16*)WAl, KDIM, N_QKV);
    }
    {
        dim3 g(DMODEL / 32, KDIM / 32);
        splitT_kernel<<<g, dim3(32, 8)>>>(W_proj, (__nv_bfloat16*)WPh, (__nv_bfloat16*)WPl, KDIM, DMODEL);
    }
    // 3) QKV GEMM
    {
        dim3 g(N_QKV / 128, M_TOK / 128);   // (48, 32)
        gemm_bf16x3_kernel<<<g, 256, GEMM_SMEM>>>(tAh, tAl, tWAh, tWAl, b_attn, qkv, N_QKV);
    }
    // 4) differential attention (fp32)
    {
        dim3 g(S_LEN / 64, B_SZ * NHEAD);
        diff_attn_kernel<<<g, 256, ATT_SMEM_BYTES>>>(qkv, amask, lam, attn);
    }
    // 5) split attention output
    {
        int n4 = (M_TOK * KDIM) / 4;
        split_kernel<<<n4 / 256, 256>>>((const float4*)attn, (uint2*)Oh, (uint2*)Ol, n4);
    }
    // 6) output projection
    {
        dim3 g(DMODEL / 128, M_TOK / 128);  // (16, 32)
        gemm_bf16x3_kernel<<<g, 256, GEMM_SMEM>>>(tOh, tOl, tWPh, tWPl, b_proj, out, DMODEL);
    }
}

// round 4
// speedup vs baseline: 3.8166x; 2.6272x over previous
#include <cuda_runtime.h>
#include <cuda_bf16.h>
#include <cuda.h>
#include <cstdint>

// Problem dims (fixed by setup_inputs)
#define B_SZ   2
#define S_LEN  2048
#define DMODEL 2048
#define NHEAD  16
#define M_TOK  (B_SZ * S_LEN)     // 4096
#define N_QKV  (3 * DMODEL)       // 6144
#define KDIM   DMODEL             // 2048
#define QSCALE 0.0883883476483184f

// ---------------- scratch (static device globals: allocation-free) ----------
__device__ unsigned short g_qkvh[(size_t)M_TOK * N_QKV];   // 50 MB
__device__ unsigned short g_qkvl[(size_t)M_TOK * N_QKV];   // 50 MB
__device__ float g_o1[(size_t)M_TOK * DMODEL];
__device__ float g_o2[(size_t)M_TOK * DMODEL];
__device__ unsigned short g_Ah[(size_t)M_TOK * KDIM];
__device__ unsigned short g_Al[(size_t)M_TOK * KDIM];
__device__ unsigned short g_WAh[(size_t)N_QKV * KDIM];
__device__ unsigned short g_WAl[(size_t)N_QKV * KDIM];
__device__ unsigned short g_WPh[(size_t)DMODEL * KDIM];
__device__ unsigned short g_WPl[(size_t)DMODEL * KDIM];
__device__ unsigned short g_Oh[(size_t)M_TOK * KDIM];
__device__ unsigned short g_Ol[(size_t)M_TOK * KDIM];

// ---------------------------------------------------------------------------
// PTX helpers (base sm_90 only — no 'a'-gated instructions)
// ---------------------------------------------------------------------------
__device__ __forceinline__ uint32_t smem_u32(const void* p) {
    uint32_t a;
    asm("{ .reg .u64 t; cvta.to.shared.u64 t, %1; cvt.u32.u64 %0, t; }" : "=r"(a) : "l"(p));
    return a;
}

#define MBARRIER_INIT(addr, cnt) \
    asm volatile("mbarrier.init.shared.b64 [%0], %1;" :: "r"((uint32_t)(addr)), "r"((uint32_t)(cnt)) : "memory")

#define MBARRIER_ARRIVE(addr) \
    asm volatile("mbarrier.arrive.shared.b64 _, [%0];" :: "r"((uint32_t)(addr)) : "memory")

#define MBARRIER_EXPECT_TX(addr, bytes) \
    asm volatile("mbarrier.arrive.expect_tx.shared.b64 _, [%0], %1;" :: "r"((uint32_t)(addr)), "r"((uint32_t)(bytes)) : "memory")

#define MBARRIER_WAIT_PARITY(mbar_smem_addr, phase_parity) do { \
    uint32_t _mbar = (uint32_t)(mbar_smem_addr); \
    uint32_t _parity = (uint32_t)(phase_parity); \
    uint32_t _done; \
    asm volatile( \
        "{\n\t.reg .pred p;\n\t" \
        "mbarrier.try_wait.parity.acquire.cta.shared::cta.b64 p, [%1], %2;\n\t" \
        "selp.b32 %0, 1, 0, p;\n\t}" \
        : "=r"(_done) : "r"(_mbar), "r"(_parity) : "memory"); \
    if (!_done) { \
        asm volatile( \
            "{\n\t.reg .pred P1;\n\t" \
            "WAIT_LOOP_%=:\n\t" \
            "mbarrier.try_wait.parity.acquire.cta.shared::cta.b64 P1, [%0], %1, 0x989680;\n\t" \
            "@P1 bra.uni WAIT_DONE_%=;\n\t" \
            "bra.uni WAIT_LOOP_%=;\n\t" \
            "WAIT_DONE_%=:\n\t}" \
            :: "r"(_mbar), "r"(_parity) : "memory"); \
    } \
} while(0)

#define MBARRIER_WAIT_PARITY_RELAXED(mbar_smem_addr, phase_parity) do { \
    uint32_t _mbar = (uint32_t)(mbar_smem_addr); \
    uint32_t _parity = (uint32_t)(phase_parity); \
    uint32_t _done; \
    asm volatile( \
        "{\n\t.reg .pred p;\n\t" \
        "mbarrier.try_wait.parity.relaxed.cta.shared::cta.b64 p, [%1], %2, 0x989680;\n\t" \
        "selp.b32 %0, 1, 0, p;\n\t}" \
        : "=r"(_done) : "r"(_mbar), "r"(_parity) : "memory"); \
    if (!_done) { \
        asm volatile( \
            "{\n\t.reg .pred P1;\n\t" \
            "WAIT_LOOP_%=:\n\t" \
            "mbarrier.try_wait.parity.relaxed.cta.shared::cta.b64 P1, [%0], %1, 0x989680;\n\t" \
            "@P1 bra.uni WAIT_DONE_%=;\n\t" \
            "bra.uni WAIT_LOOP_%=;\n\t" \
            "WAIT_DONE_%=:\n\t}" \
            :: "r"(_mbar), "r"(_parity) : "memory"); \
    } \
} while(0)

__device__ __forceinline__ void tma2d(uint32_t dst, const void* map, int x, int y, uint32_t mbar) {
    asm volatile(
        "cp.async.bulk.tensor.2d.shared::cta.global.tile.mbarrier::complete_tx::bytes "
        "[%0], [%1, {%2, %3}], [%4];"
        :: "r"(dst), "l"(map), "r"(x), "r"(y), "r"(mbar) : "memory");
}

__device__ __forceinline__ void ldsm4(uint32_t* r, uint32_t addr) {
    asm volatile("ldmatrix.sync.aligned.m8n8.x4.shared.b16 {%0,%1,%2,%3}, [%4];"
                 : "=r"(r[0]), "=r"(r[1]), "=r"(r[2]), "=r"(r[3]) : "r"(addr));
}
__device__ __forceinline__ void ldsm4t(uint32_t* r, uint32_t addr) {
    asm volatile("ldmatrix.sync.aligned.m8n8.x4.trans.shared.b16 {%0,%1,%2,%3}, [%4];"
                 : "=r"(r[0]), "=r"(r[1]), "=r"(r[2]), "=r"(r[3]) : "r"(addr));
}

__device__ __forceinline__ void mma_bf16(float* d, const uint32_t* a, uint32_t b0, uint32_t b1) {
    asm volatile(
        "mma.sync.aligned.m16n8k16.row.col.f32.bf16.bf16.f32 "
        "{%0,%1,%2,%3}, {%4,%5,%6,%7}, {%8,%9}, {%0,%1,%2,%3};"
        : "+f"(d[0]), "+f"(d[1]), "+f"(d[2]), "+f"(d[3])
        : "r"(a[0]), "r"(a[1]), "r"(a[2]), "r"(a[3]), "r"(b0), "r"(b1));
}

__device__ __forceinline__ uint32_t pack2bf(float a, float b) {
    __nv_bfloat162 t = __floats2bfloat162_rn(a, b);
    return *reinterpret_cast<uint32_t*>(&t);
}

// Fast exp on the FMA pipe (no MUFU). Valid for x <= 0 (clamped below -80).
// rel err ~1.2e-7.
__device__ __forceinline__ float fexp(float x) {
    x = fmaxf(x, -80.0f);
    float t = x * 1.4426950408889634f;
    float z = t + 12582912.0f;                      // round-to-nearest-int trick
    int n = __float_as_int(z) - 0x4b400000;
    float f = t - (z - 12582912.0f);                // f in [-0.5, 0.5]
    float u = f * 0.6931471805599453f;
    float r = 1.3888889e-3f;
    r = fmaf(r, u, 8.3333338e-3f);
    r = fmaf(r, u, 4.1666668e-2f);
    r = fmaf(r, u, 1.6666667e-1f);
    r = fmaf(r, u, 0.5f);
    r = fmaf(r, u, 1.0f);
    r = fmaf(r, u, 1.0f);
    return r * __int_as_float((n + 127) << 23);
}

// ---------------------------------------------------------------------------
// bf16x3 GEMM:  C[M,N] = A[M,K] @ B[N,K]^T + bias
// MODE 0: fp32 out to C.  MODE 1: bf16 hi/lo out to Ch/Cl, q-columns pre-scaled.
// CTA 128x128, K-chunk 64, 3-stage TMA, 8 warps, mma.sync m16n8k16.
// ---------------------------------------------------------------------------
#define GSTAGES     3
#define GCHUNKS     32
#define GTILE_BYTES 16384
#define GSTAGE_BYTES (4 * GTILE_BYTES)
#define GSM_DATA    1024
#define GEMM_SMEM   (GSM_DATA + GSTAGES * GSTAGE_BYTES)

template <int MODE>
__global__ __launch_bounds__(256, 1)
void gemm_bf16x3_kernel(const __grid_constant__ CUtensorMap tmAh,
                        const __grid_constant__ CUtensorMap tmAl,
                        const __grid_constant__ CUtensorMap tmBh,
                        const __grid_constant__ CUtensorMap tmBl,
                        const float* __restrict__ bias,
                        float* __restrict__ C,
                        unsigned short* __restrict__ Ch,
                        unsigned short* __restrict__ Cl,
                        int N)
{
    extern __shared__ __align__(1024) char gsm[];
    const uint32_t sb = smem_u32(gsm);
    const int tid = threadIdx.x;
    const int lane = tid & 31;
    const int wid = tid >> 5;
    const int row0 = blockIdx.y * 128;
    const int col0 = blockIdx.x * 128;
    const int wm = (wid & 3) * 32;
    const int wn = (wid >> 2) * 64;

    if (tid == 0) {
#pragma unroll
        for (int s = 0; s < GSTAGES; ++s) {
            MBARRIER_INIT(sb + 8 * s, 1);
            MBARRIER_INIT(sb + 24 + 8 * s, 256);
        }
    }
    __syncthreads();

    if (tid == 0) {
#pragma unroll
        for (int p = 0; p < GSTAGES; ++p) {
            const uint32_t st = sb + GSM_DATA + p * GSTAGE_BYTES;
            MBARRIER_EXPECT_TX(sb + 8 * p, GSTAGE_BYTES);
            const int k0 = p * 64;
            tma2d(st,                  &tmAh, k0, row0, sb + 8 * p);
            tma2d(st + GTILE_BYTES,    &tmAl, k0, row0, sb + 8 * p);
            tma2d(st + 2 * GTILE_BYTES,&tmBh, k0, col0, sb + 8 * p);
            tma2d(st + 3 * GTILE_BYTES,&tmBl, k0, col0, sb + 8 * p);
        }
    }

    float acc[2][8][4];
#pragma unroll
    for (int i = 0; i < 2; i++)
#pragma unroll
        for (int j = 0; j < 8; j++)
#pragma unroll
            for (int k = 0; k < 4; k++) acc[i][j][k] = 0.f;

    const uint32_t cbase = (lane >> 4) * 16;
    uint32_t aRB[2], aMask[2], bRB[4], bMask[4];
#pragma unroll
    for (int mt = 0; mt < 2; ++mt) {
        const int r = wm + mt * 16 + (lane & 15);
        aRB[mt] = (uint32_t)r * 128;
        aMask[mt] = (uint32_t)((r & 7) << 4);
    }
#pragma unroll
    for (int j = 0; j < 4; ++j) {
        const int r = wn + j * 16 + (lane & 15);
        bRB[j] = (uint32_t)r * 128;
        bMask[j] = (uint32_t)((r & 7) << 4);
    }

    for (int c = 0; c < GCHUNKS; ++c) {
        const int u = c / 3;
        const int s = c - u * 3;
        MBARRIER_WAIT_PARITY(sb + 8 * s, (uint32_t)(u & 1));

        const uint32_t stA  = sb + GSM_DATA + s * GSTAGE_BYTES;
        const uint32_t stAl = stA + GTILE_BYTES;
        const uint32_t stB  = stA + 2 * GTILE_BYTES;
        const uint32_t stBl = stA + 3 * GTILE_BYTES;

#pragma unroll
        for (int kk = 0; kk < 4; ++kk) {
            const uint32_t kb = cbase + kk * 32;
            uint32_t ah[2][4], al[2][4], bh[4][4], bl[4][4];
#pragma unroll
            for (int mt = 0; mt < 2; ++mt) {
                ldsm4(ah[mt], stA  + aRB[mt] + (kb ^ aMask[mt]));
                ldsm4(al[mt], stAl + aRB[mt] + (kb ^ aMask[mt]));
            }
#pragma unroll
            for (int j = 0; j < 4; ++j) {
                ldsm4(bh[j], stB  + bRB[j] + (kb ^ bMask[j]));
                ldsm4(bl[j], stBl + bRB[j] + (kb ^ bMask[j]));
            }
#pragma unroll
            for (int mt = 0; mt < 2; ++mt) {
#pragma unroll
                for (int j = 0; j < 4; ++j) {
                    mma_bf16(acc[mt][2 * j],     ah[mt], bh[j][0], bh[j][2]);
                    mma_bf16(acc[mt][2 * j],     ah[mt], bl[j][0], bl[j][2]);
                    mma_bf16(acc[mt][2 * j],     al[mt], bh[j][0], bh[j][2]);
                    mma_bf16(acc[mt][2 * j + 1], ah[mt], bh[j][1], bh[j][3]);
                    mma_bf16(acc[mt][2 * j + 1], ah[mt], bl[j][1], bl[j][3]);
                    mma_bf16(acc[mt][2 * j + 1], al[mt], bh[j][1], bh[j][3]);
                }
            }
        }

        MBARRIER_ARRIVE(sb + 24 + 8 * s);

        const int p = c + GSTAGES;
        if (tid == 0 && p < GCHUNKS) {
            const int up = p / 3;
            MBARRIER_WAIT_PARITY_RELAXED(sb + 24 + 8 * s, (uint32_t)((up & 1) ^ 1));
            const uint32_t st = sb + GSM_DATA + s * GSTAGE_BYTES;
            MBARRIER_EXPECT_TX(sb + 8 * s, GSTAGE_BYTES);
            const int k0 = p * 64;
            tma2d(st,                   &tmAh, k0, row0, sb + 8 * s);
            tma2d(st + GTILE_BYTES,     &tmAl, k0, row0, sb + 8 * s);
            tma2d(st + 2 * GTILE_BYTES, &tmBh, k0, col0, sb + 8 * s);
            tma2d(st + 3 * GTILE_BYTES, &tmBl, k0, col0, sb + 8 * s);
        }
    }

    // Epilogue
    const int rr = lane >> 2;
    const int cc = (lane & 3) * 2;
#pragma unroll
    for (int mt = 0; mt < 2; ++mt) {
        const int mrow = row0 + wm + mt * 16 + rr;
#pragma unroll
        for (int nt = 0; nt < 8; ++nt) {
            const int n = col0 + wn + nt * 8 + cc;
            const float2 bb = *(const float2*)(bias + n);
            float v00 = acc[mt][nt][0] + bb.x, v01 = acc[mt][nt][1] + bb.y;
            float v10 = acc[mt][nt][2] + bb.x, v11 = acc[mt][nt][3] + bb.y;
            if (MODE == 0) {
                *(float2*)(C + (size_t)mrow * N + n) = make_float2(v00, v01);
                *(float2*)(C + (size_t)(mrow + 8) * N + n) = make_float2(v10, v11);
            } else {
                const float sc = (n < 2048) ? QSCALE : 1.0f;
                v00 *= sc; v01 *= sc; v10 *= sc; v11 *= sc;
                float h00 = __bfloat162float(__float2bfloat16(v00));
                float h01 = __bfloat162float(__float2bfloat16(v01));
                float h10 = __bfloat162float(__float2bfloat16(v10));
                float h11 = __bfloat162float(__float2bfloat16(v11));
                *(uint32_t*)(Ch + (size_t)mrow * N + n)       = pack2bf(h00, h01);
                *(uint32_t*)(Cl + (size_t)mrow * N + n)       = pack2bf(v00 - h00, v01 - h01);
                *(uint32_t*)(Ch + (size_t)(mrow + 8) * N + n) = pack2bf(h10, h11);
                *(uint32_t*)(Cl + (size_t)(mrow + 8) * N + n) = pack2bf(v10 - h10, v11 - h11);
            }
        }
    }
}

// ---------------------------------------------------------------------------
// Differential flash attention, mma.sync bf16x3.
// Grid: (S/128, B*H, 2 streams). 256 threads = 8 warps, each warp 16 q-rows.
// One stream per blockIdx.z; outputs o/l to o1buf / o2buf.
// ---------------------------------------------------------------------------
#define AT_STAGE_BYTES 49152           // Kh 8K | Kl 8K | Vh 16K | Vl 16K
#define AT_SMEM (49152 + 2 * AT_STAGE_BYTES)   // 147456

__global__ __launch_bounds__(256, 1)
void diff_attn_mma_kernel(const __grid_constant__ CUtensorMap tmQh,
                          const __grid_constant__ CUtensorMap tmQl,
                          const __grid_constant__ CUtensorMap tmKh,
                          const __grid_constant__ CUtensorMap tmKl,
                          const float* __restrict__ amask,
                          float* __restrict__ o1buf,
                          float* __restrict__ o2buf)
{
    extern __shared__ __align__(1024) char asmem[];
    const uint32_t sb = smem_u32(asmem);
    const int tid = threadIdx.x, lane = tid & 31, w = tid >> 5;
    const int qb = blockIdx.x, bh = blockIdx.y, strm = blockIdx.z;
    const int b = bh >> 4, h = bh & 15;
    const int q0 = qb * 128;
    const int tokbase = b * S_LEN;

    const uint32_t MB_Q = sb, MB_F0 = sb + 8, MB_F1 = sb + 16, MB_E0 = sb + 24, MB_E1 = sb + 32;
    float* maskSm = (float*)(asmem + 64);            // 2048 floats = 8KB
    const uint32_t QH = sb + 16384, QL = QH + 16384;
    const uint32_t ST0 = sb + 49152;

    if (tid == 0) {
        MBARRIER_INIT(MB_Q, 1);
        MBARRIER_INIT(MB_F0, 1); MBARRIER_INIT(MB_F1, 1);
        MBARRIER_INIT(MB_E0, 256); MBARRIER_INIT(MB_E1, 256);
    }
    {
        const float4* mp = (const float4*)(amask + tokbase);
        float4* ms = (float4*)maskSm;
#pragma unroll
        for (int i = tid; i < 512; i += 256) {
            float4 v = mp[i];
            v.x = (1.f - v.x) * -10000.f;
            v.y = (1.f - v.y) * -10000.f;
            v.z = (1.f - v.z) * -10000.f;
            v.w = (1.f - v.w) * -10000.f;
            ms[i] = v;
        }
    }
    __syncthreads();

    const int qcol = strm * 1024 + h * 64;
    const int kcol = 2048 + strm * 1024 + h * 64;
    const int vcol = 4096 + h * 128;

    if (tid == 0) {
        MBARRIER_EXPECT_TX(MB_Q, 32768);
        tma2d(QH, &tmQh, qcol, tokbase + q0, MB_Q);
        tma2d(QL, &tmQl, qcol, tokbase + q0, MB_Q);
#pragma unroll
        for (int s = 0; s < 2; ++s) {
            const uint32_t st = ST0 + s * AT_STAGE_BYTES;
            const uint32_t fb = s ? MB_F1 : MB_F0;
            MBARRIER_EXPECT_TX(fb, AT_STAGE_BYTES);
            const int k0 = tokbase + s * 64;
            tma2d(st,         &tmKh, kcol,      k0, fb);
            tma2d(st + 8192,  &tmKl, kcol,      k0, fb);
            tma2d(st + 16384, &tmKh, vcol,      k0, fb);
            tma2d(st + 24576, &tmKh, vcol + 64, k0, fb);
            tma2d(st + 32768, &tmKl, vcol,      k0, fb);
            tma2d(st + 40960, &tmKl, vcol + 64, k0, fb);
        }
    }

    // Q fragments (held in regs for the whole kernel)
    MBARRIER_WAIT_PARITY(MB_Q, 0);
    uint32_t qh[4][4], ql[4][4];
    {
        const int r = 16 * w + (lane & 15);
        const uint32_t rb = (uint32_t)r * 128;
        const uint32_t msk = (uint32_t)((r & 7) << 4);
        const uint32_t cb = (uint32_t)(lane >> 4) * 16;
#pragma unroll
        for (int kk = 0; kk < 4; ++kk) {
            ldsm4(qh[kk], QH + rb + ((cb + kk * 32) ^ msk));
            ldsm4(ql[kk], QL + rb + ((cb + kk * 32) ^ msk));
        }
    }

    float o[16][4];
#pragma unroll
    for (int i = 0; i < 16; i++)
#pragma unroll
        for (int j = 0; j < 4; j++) o[i][j] = 0.f;
    float m0 = -1e30f, m1 = -1e30f, l0 = 0.f, l1 = 0.f;

    uint32_t kRB[4], kMask[4];
#pragma unroll
    for (int g = 0; g < 4; ++g) {
        const int r = 16 * g + (lane & 15);
        kRB[g] = (uint32_t)r * 128;
        kMask[g] = (uint32_t)((r & 7) << 4);
    }
    const uint32_t cb = (uint32_t)(lane >> 4) * 16;

    for (int kb = 0; kb < 32; ++kb) {
        const int s = kb & 1, u = kb >> 1;
        const uint32_t FULL = s ? MB_F1 : MB_F0;
        const uint32_t EMPTY = s ? MB_E1 : MB_E0;
        const uint32_t ST = ST0 + s * AT_STAGE_BYTES;
        MBARRIER_WAIT_PARITY(FULL, (uint32_t)(u & 1));

        // ---- scores: 3-term bf16 split MMA ----
        float scf[8][4];
#pragma unroll
        for (int t = 0; t < 8; t++)
#pragma unroll
            for (int j = 0; j < 4; j++) scf[t][j] = 0.f;

#pragma unroll
        for (int kk = 0; kk < 4; ++kk) {
            uint32_t kh[4][4], kl[4][4];
#pragma unroll
            for (int g = 0; g < 4; ++g) {
                const uint32_t a = cb + kk * 32;
                ldsm4(kh[g], ST + kRB[g] + (a ^ kMask[g]));
                ldsm4(kl[g], ST + 8192 + kRB[g] + (a ^ kMask[g]));
            }
#pragma unroll
            for (int g = 0; g < 4; ++g) {
                mma_bf16(scf[2 * g],     qh[kk], kh[g][0], kh[g][2]);
                mma_bf16(scf[2 * g],     qh[kk], kl[g][0], kl[g][2]);
                mma_bf16(scf[2 * g],     ql[kk], kh[g][0], kh[g][2]);
                mma_bf16(scf[2 * g + 1], qh[kk], kh[g][1], kh[g][3]);
                mma_bf16(scf[2 * g + 1], qh[kk], kl[g][1], kl[g][3]);
                mma_bf16(scf[2 * g + 1], ql[kk], kh[g][1], kh[g][3]);
            }
        }

        // ---- mask + dual-row online softmax ----
        const int kbase = kb * 64 + 2 * (lane & 3);
        float nm0 = m0, nm1 = m1;
#pragma unroll
        for (int t = 0; t < 8; ++t) {
            const float mv0 = maskSm[kbase + 8 * t];
            const float mv1 = maskSm[kbase + 8 * t + 1];
            scf[t][0] += mv0; scf[t][1] += mv1;
            scf[t][2] += mv0; scf[t][3] += mv1;
            nm0 = fmaxf(nm0, fmaxf(scf[t][0], scf[t][1]));
            nm1 = fmaxf(nm1, fmaxf(scf[t][2], scf[t][3]));
        }
        nm0 = fmaxf(nm0, __shfl_xor_sync(0xffffffffu, nm0, 1));
        nm0 = fmaxf(nm0, __shfl_xor_sync(0xffffffffu, nm0, 2));
        nm1 = fmaxf(nm1, __shfl_xor_sync(0xffffffffu, nm1, 1));
        nm1 = fmaxf(nm1, __shfl_xor_sync(0xffffffffu, nm1, 2));
        const float a0 = fexp(m0 - nm0), a1 = fexp(m1 - nm1);
        m0 = nm0; m1 = nm1;
#pragma unroll
        for (int nt = 0; nt < 16; ++nt) {
            o[nt][0] *= a0; o[nt][1] *= a0;
            o[nt][2] *= a1; o[nt][3] *= a1;
        }

        uint32_t pha[4][4], pla[4][4];
        float rs0 = 0.f, rs1 = 0.f;
#pragma unroll
        for (int t = 0; t < 8; ++t) {
            const float e0 = fexp(scf[t][0] - m0), e1 = fexp(scf[t][1] - m0);
            const float e2 = fexp(scf[t][2] - m1), e3 = fexp(scf[t][3] - m1);
            rs0 += e0 + e1; rs1 += e2 + e3;
            const float h0 = __bfloat162float(__float2bfloat16(e0));
            const float h1 = __bfloat162float(__float2bfloat16(e1));
            const float h2 = __bfloat162float(__float2bfloat16(e2));
            const float h3 = __bfloat162float(__float2bfloat16(e3));
            pha[t >> 1][2 * (t & 1)]     = pack2bf(h0, h1);
            pha[t >> 1][2 * (t & 1) + 1] = pack2bf(h2, h3);
            pla[t >> 1][2 * (t & 1)]     = pack2bf(e0 - h0, e1 - h1);
            pla[t >> 1][2 * (t & 1) + 1] = pack2bf(e2 - h2, e3 - h3);
        }
        rs0 += __shfl_xor_sync(0xffffffffu, rs0, 1);
        rs0 += __shfl_xor_sync(0xffffffffu, rs0, 2);
        rs1 += __shfl_xor_sync(0xffffffffu, rs1, 1);
        rs1 += __shfl_xor_sync(0xffffffffu, rs1, 2);
        l0 = l0 * a0 + rs0;
        l1 = l1 * a1 + rs1;

        // ---- PV: 3-term split, V via trans ldmatrix ----
#pragma unroll
        for (int kk = 0; kk < 4; ++kk) {
            const int r = 16 * kk + (lane & 15);
            const uint32_t vrb = (uint32_t)r * 128;
            const uint32_t vmsk = (uint32_t)((r & 7) << 4);
#pragma unroll
            for (int g = 0; g < 8; ++g) {
                const uint32_t base = ST + 16384 + ((g >> 2) ? 8192u : 0u);
                const uint32_t a = ((uint32_t)((g & 3) * 32) + cb) ^ vmsk;
                uint32_t vh[4], vl[4];
                ldsm4t(vh, base + vrb + a);
                ldsm4t(vl, base + 16384 + vrb + a);
                mma_bf16(o[2 * g],     pha[kk], vh[0], vh[1]);
                mma_bf16(o[2 * g],     pla[kk], vh[0], vh[1]);
                mma_bf16(o[2 * g],     pha[kk], vl[0], vl[1]);
                mma_bf16(o[2 * g + 1], pha[kk], vh[2], vh[3]);
                mma_bf16(o[2 * g + 1], pla[kk], vh[2], vh[3]);
                mma_bf16(o[2 * g + 1], pha[kk], vl[2], vl[3]);
            }
        }

        MBARRIER_ARRIVE(EMPTY);

        if (tid == 0 && kb + 2 < 32) {
            const int p = kb + 2;
            MBARRIER_WAIT_PARITY_RELAXED(EMPTY, (uint32_t)((((p >> 1) & 1) ^ 1)));
            MBARRIER_EXPECT_TX(FULL, AT_STAGE_BYTES);
            const int k0 = tokbase + p * 64;
            tma2d(ST,         &tmKh, kcol,      k0, FULL);
            tma2d(ST + 8192,  &tmKl, kcol,      k0, FULL);
            tma2d(ST + 16384, &tmKh, vcol,      k0, FULL);
            tma2d(ST + 24576, &tmKh, vcol + 64, k0, FULL);
            tma2d(ST + 32768, &tmKl, vcol,      k0, FULL);
            tma2d(ST + 40960, &tmKl, vcol + 64, k0, FULL);
        }
    }

    // ---- normalize + store ----
    const float inv0 = 1.f / l0, inv1 = 1.f / l1;
    float* ob = strm ? o2buf : o1buf;
    const int row = tokbase + q0 + 16 * w + (lane >> 2);
    float* p0 = ob + (size_t)row * DMODEL + h * 128 + 2 * (lane & 3);
    float* p1 = p0 + 8 * DMODEL;
#pragma unroll
    for (int nt = 0; nt < 16; ++nt) {
        *(float2*)(p0 + 8 * nt) = make_float2(o[nt][0] * inv0, o[nt][1] * inv0);
        *(float2*)(p1 + 8 * nt) = make_float2(o[nt][2] * inv1, o[nt][3] * inv1);
    }
}

// ---------------------------------------------------------------------------
// combine (o1 - lam*o2) + bf16 hi/lo split for proj GEMM input
// ---------------------------------------------------------------------------
__global__ __launch_bounds__(256)
void combine_split_kernel(const float4* __restrict__ o1, const float4* __restrict__ o2,
                          const float* __restrict__ lamp,
                          uint2* __restrict__ hi, uint2* __restrict__ lo, int n4)
{
    int i = blockIdx.x * blockDim.x + threadIdx.x;
    if (i >= n4) return;
    const float lam = *lamp;
    float4 a = o1[i], c = o2[i];
    float v0 = a.x - lam * c.x, v1 = a.y - lam * c.y;
    float v2 = a.z - lam * c.z, v3 = a.w - lam * c.w;
    float h0 = __bfloat162float(__float2bfloat16(v0));
    float h1 = __bfloat162float(__float2bfloat16(v1));
    float h2 = __bfloat162float(__float2bfloat16(v2));
    float h3 = __bfloat162float(__float2bfloat16(v3));
    uint2 H, L;
    H.x = pack2bf(h0, h1); H.y = pack2bf(h2, h3);
    L.x = pack2bf(v0 - h0, v1 - h1); L.y = pack2bf(v2 - h2, v3 - h3);
    hi[i] = H;
    lo[i] = L;
}

// fp32 -> (hi, lo) bf16 split, elementwise
__global__ __launch_bounds__(256)
void split_kernel(const float4* __restrict__ x, uint2* __restrict__ hi,
                  uint2* __restrict__ lo, int n4)
{
    int i = blockIdx.x * blockDim.x + threadIdx.x;
    if (i >= n4) return;
    float4 v = x[i];
    float h0 = __bfloat162float(__float2bfloat16(v.x));
    float h1 = __bfloat162float(__float2bfloat16(v.y));
    float h2 = __bfloat162float(__float2bfloat16(v.z));
    float h3 = __bfloat162float(__float2bfloat16(v.w));
    uint2 H, L;
    H.x = pack2bf(h0, h1); H.y = pack2bf(h2, h3);
    L.x = pack2bf(v.x - h0, v.y - h1); L.y = pack2bf(v.z - h2, v.w - h3);
    hi[i] = H;
    lo[i] = L;
}

// fp32 W[K][N] -> transposed bf16 split hiT[N][K], loT[N][K]
__global__ __launch_bounds__(256)
void splitT_kernel(const float* __restrict__ W, __nv_bfloat16* __restrict__ hiT,
                   __nv_bfloat16* __restrict__ loT, int K, int N)
{
    __shared__ float t[32][33];
    const int tx = threadIdx.x, ty = threadIdx.y;
    const int n0 = blockIdx.x * 32, k0 = blockIdx.y * 32;
#pragma unroll
    for (int r = 0; r < 4; ++r)
        t[ty + 8 * r][tx] = W[(size_t)(k0 + ty + 8 * r) * N + n0 + tx];
    __syncthreads();
#pragma unroll
    for (int r = 0; r < 4; ++r) {
        const int nn = ty + 8 * r;
        float v = t[tx][nn];
        __nv_bfloat16 hbf = __float2bfloat16(v);
        __nv_bfloat16 lbf = __float2bfloat16(v - __bfloat162float(hbf));
        const size_t off = (size_t)(n0 + nn) * K + k0 + tx;
        hiT[off] = hbf;
        loT[off] = lbf;
    }
}

// ---------------------------------------------------------------------------
// Host side
// ---------------------------------------------------------------------------
typedef CUresult (*PFN_tmEncode)(
    CUtensorMap*, CUtensorMapDataType, cuuint32_t, void*,
    const cuuint64_t*, const cuuint64_t*, const cuuint32_t*, const cuuint32_t*,
    CUtensorMapInterleave, CUtensorMapSwizzle, CUtensorMapL2promotion,
    CUtensorMapFloatOOBfill);

static void make_map(PFN_tmEncode fn, CUtensorMap* m, void* ptr,
                     unsigned long long rows, unsigned long long cols,
                     unsigned box0, unsigned box1)
{
    cuuint64_t dims[2]    = {(cuuint64_t)cols, (cuuint64_t)rows};
    cuuint64_t strides[1] = {(cuuint64_t)cols * 2};
    cuuint32_t box[2]     = {box0, box1};
    cuuint32_t es[2]      = {1u, 1u};
    fn(m, CU_TENSOR_MAP_DATA_TYPE_BFLOAT16, 2, ptr, dims, strides, box, es,
       CU_TENSOR_MAP_INTERLEAVE_NONE, CU_TENSOR_MAP_SWIZZLE_128B,
       CU_TENSOR_MAP_L2_PROMOTION_L2_128B, CU_TENSOR_MAP_FLOAT_OOB_FILL_NONE);
}

extern "C" void kernel_launch(void* const* d_in, const int* in_sizes, int n_in,
                              void* d_out, int out_size)
{
    const float* hidden = (const float*)d_in[0];
    const float* amask  = (const float*)d_in[1];
    const float* W_attn = (const float*)d_in[2];
    const float* b_attn = (const float*)d_in[3];
    const float* W_proj = (const float*)d_in[4];
    const float* b_proj = (const float*)d_in[5];
    const float* lam    = (const float*)d_in[6];
    float* out = (float*)d_out;

    void *qkvh, *qkvl, *o1, *o2, *Ah, *Al, *WAh, *WAl, *WPh, *WPl, *Oh, *Ol;
    cudaGetSymbolAddress(&qkvh, g_qkvh); cudaGetSymbolAddress(&qkvl, g_qkvl);
    cudaGetSymbolAddress(&o1, g_o1);     cudaGetSymbolAddress(&o2, g_o2);
    cudaGetSymbolAddress(&Ah, g_Ah);     cudaGetSymbolAddress(&Al, g_Al);
    cudaGetSymbolAddress(&WAh, g_WAh);   cudaGetSymbolAddress(&WAl, g_WAl);
    cudaGetSymbolAddress(&WPh, g_WPh);   cudaGetSymbolAddress(&WPl, g_WPl);
    cudaGetSymbolAddress(&Oh, g_Oh);     cudaGetSymbolAddress(&Ol, g_Ol);

    void* fnp = nullptr;
    cudaDriverEntryPointQueryResult qres;
    cudaGetDriverEntryPointByVersion("cuTensorMapEncodeTiled", &fnp, 12000,
                                     cudaEnableDefault, &qres);
    PFN_tmEncode enc = (PFN_tmEncode)fnp;

    CUtensorMap tAh, tAl, tWAh, tWAl, tWPh, tWPl, tOh, tOl;
    CUtensorMap tQh, tQl, tKh, tKl;
    make_map(enc, &tAh,  Ah,  M_TOK, KDIM, 64, 128);
    make_map(enc, &tAl,  Al,  M_TOK, KDIM, 64, 128);
    make_map(enc, &tWAh, WAh, N_QKV, KDIM, 64, 128);
    make_map(enc, &tWAl, WAl, N_QKV, KDIM, 64, 128);
    make_map(enc, &tWPh, WPh, DMODEL, KDIM, 64, 128);
    make_map(enc, &tWPl, WPl, DMODEL, KDIM, 64, 128);
    make_map(enc, &tOh,  Oh,  M_TOK, KDIM, 64, 128);
    make_map(enc, &tOl,  Ol,  M_TOK, KDIM, 64, 128);
    make_map(enc, &tQh,  qkvh, M_TOK, N_QKV, 64, 128);
    make_map(enc, &tQl,  qkvl, M_TOK, N_QKV, 64, 128);
    make_map(enc, &tKh,  qkvh, M_TOK, N_QKV, 64, 64);
    make_map(enc, &tKl,  qkvl, M_TOK, N_QKV, 64, 64);

    cudaFuncSetAttribute(gemm_bf16x3_kernel<0>,
                         cudaFuncAttributeMaxDynamicSharedMemorySize, GEMM_SMEM);
    cudaFuncSetAttribute(gemm_bf16x3_kernel<1>,
                         cudaFuncAttributeMaxDynamicSharedMemorySize, GEMM_SMEM);
    cudaFuncSetAttribute(diff_attn_mma_kernel,
                         cudaFuncAttributeMaxDynamicSharedMemorySize, AT_SMEM);

    // 1) split hidden -> Ah/Al
    {
        int n4 = (M_TOK * KDIM) / 4;
        split_kernel<<<n4 / 256, 256>>>((const float4*)hidden, (uint2*)Ah, (uint2*)Al, n4);
    }
    // 2) split+transpose weights
    {
        dim3 g(N_QKV / 32, KDIM / 32);
        splitT_kernel<<<g, dim3(32, 8)>>>(W_attn, (__nv_bfloat16*)WAh, (__nv_bfloat16*)WAl, KDIM, N_QKV);
    }
    {
        dim3 g(DMODEL / 32, KDIM / 32);
        splitT_kernel<<<g, dim3(32, 8)>>>(W_proj, (__nv_bfloat16*)WPh, (__nv_bfloat16*)WPl, KDIM, DMODEL);
    }
    // 3) QKV GEMM -> bf16 hi/lo (q pre-scaled)
    {
        dim3 g(N_QKV / 128, M_TOK / 128);
        gemm_bf16x3_kernel<1><<<g, 256, GEMM_SMEM>>>(tAh, tAl, tWAh, tWAl, b_attn,
                                                     nullptr, (unsigned short*)qkvh,
                                                     (unsigned short*)qkvl, N_QKV);
    }
    // 4) differential attention (both streams)
    {
        dim3 g(S_LEN / 128, B_SZ * NHEAD, 2);
        diff_attn_mma_kernel<<<g, 256, AT_SMEM>>>(tQh, tQl, tKh, tKl, amask,
                                                  (float*)o1, (float*)o2);
    }
    // 5) combine + split for proj
    {
        int n4 = (M_TOK * DMODEL) / 4;
        combine_split_kernel<<<n4 / 256, 256>>>((const float4*)o1, (const float4*)o2,
                                                lam, (uint2*)Oh, (uint2*)Ol, n4);
    }
    // 6) output projection (fp32 out)
    {
        dim3 g(DMODEL / 128, M_TOK / 128);
        gemm_bf16x3_kernel<0><<<g, 256, GEMM_SMEM>>>(tOh, tOl, tWPh, tWPl, b_proj,
                                                     out, nullptr, nullptr, DMODEL);
    }
}